// round 15
// baseline (speedup 1.0000x reference)
#include <cuda_runtime.h>
#include <cuda_bf16.h>
#include <math.h>

#define NCLS 9
#define CCH  768
#define PIX  131072     // 8 * 128 * 128 downsampled pixels
#define PLANE 16384     // 128*128
#define CT   3          // channels per k_sums tile (768 = 256 * 3)

// ---------------- scratch (device globals; no allocation allowed) -------------
__device__ float         g_sums_part[8 * NCLS * CCH];   // per-batch partial sums
__device__ int           g_counts[NCLS];
__device__ unsigned char g_labels[PIX];
__device__ float         g_d[NCLS * PIX];               // 4.7 MB e-matrix (pre-norm)
__device__ float         g_rssq_part[NCLS * 256];
__device__ float         g_scale[NCLS];
__device__ float         g_partials[128];
__device__ int           g_is_i32;

// ---------------- f32x2 packed helpers ----------------------------------------
__device__ __forceinline__ unsigned long long pack2(float x, float y) {
    unsigned long long d;
    asm("mov.b64 %0, {%1, %2};" : "=l"(d) : "f"(x), "f"(y));
    return d;
}
__device__ __forceinline__ void unpack2(unsigned long long v, float& x, float& y) {
    asm("mov.b64 {%0, %1}, %2;" : "=f"(x), "=f"(y) : "l"(v));
}
__device__ __forceinline__ unsigned long long ffma2(unsigned long long a,
                                                    unsigned long long b,
                                                    unsigned long long c) {
    unsigned long long d;
    asm("fma.rn.f32x2 %0, %1, %2, %3;" : "=l"(d) : "l"(a), "l"(b), "l"(c));
    return d;
}

// ---------------- K_init: zero counters + gt dtype probe ----------------------
__global__ void k_init(const int* __restrict__ gt32) {
    int tid = threadIdx.x;
    if (tid < NCLS) g_counts[tid] = 0;
    // int64 gt (little-endian): odd 32-bit words are all 0.
    // int32 gt: odd words are labels in [0,9): P(all 2048 zero) ~ (1/9)^2048.
    int f = 0;
    for (int i = tid; i < 2048; i += 256) f |= gt32[2 * i + 1];
    __shared__ int sf;
    if (tid == 0) sf = 0;
    __syncthreads();
    if (f) atomicOr(&sf, 1);
    __syncthreads();
    if (tid == 0) g_is_i32 = (sf != 0);
}

// ---------------- K0: downsampled labels + histogram ---------------------------
__global__ void k_labels(const int* __restrict__ gt32) {
    __shared__ int sh[NCLS];
    int tid = threadIdx.x;
    if (tid < NCLS) sh[tid] = 0;
    __syncthreads();
    int n = blockIdx.x * 256 + tid;                 // grid = 512 blocks
    int b = n >> 14, r = n & (PLANE - 1);
    int h = r >> 7, w = r & 127;
    int idx = b * 262144 + h * 2048 + w * 4;        // gt[b, 4h, 4w] element index
    int lab = g_is_i32 ? gt32[idx] : gt32[2 * idx]; // int64: low word
    g_labels[n] = (unsigned char)lab;
    atomicAdd(&sh[lab], 1);
    __syncthreads();
    if (tid < NCLS) atomicAdd(&g_counts[tid], sh[tid]);
}

// ---------------- K1: per-class channel sums (register one-hot accumulate) -----
// grid = 2048: bid = b + 8*ctile (ctile in [0,256), CT=3 channels each).
// Each block owns g_sums_part[b][*][c0..c0+2] exclusively: no atomics.
// float4-widened single-prefetch structure (validated 79.6us, DRAM 64.6%).
__global__ void __launch_bounds__(256, 2) k_sums(const float* __restrict__ feat) {
    int bid = blockIdx.x;
    int b = bid & 7;
    int c0 = (bid >> 3) * CT;
    int tid = threadIdx.x, w = tid >> 5, lane = tid & 31;
    const float* base = feat + (size_t)(b * CCH + c0) * PLANE;
    const unsigned int* lab32 = (const unsigned int*)(g_labels + b * PLANE);

    unsigned long long acc[NCLS][CT];
#pragma unroll
    for (int k = 0; k < NCLS; k++)
#pragma unroll
        for (int j = 0; j < CT; j++) acc[k][j] = 0ULL;

    int pix0 = w * 2048 + lane * 4;

    // prefetch group 0 (128 px per warp per group)
    unsigned int un = lab32[pix0 >> 2];
    float4 vn[CT];
#pragma unroll
    for (int j = 0; j < CT; j++) vn[j] = *(const float4*)(base + j * PLANE + pix0);

#pragma unroll 2
    for (int g = 0; g < 16; ++g) {
        unsigned int u = un;
        float4 v[CT];
#pragma unroll
        for (int j = 0; j < CT; j++) v[j] = vn[j];
        if (g < 15) {
            int p2 = pix0 + (g + 1) * 128;
            un = lab32[p2 >> 2];
#pragma unroll
            for (int j = 0; j < CT; j++) vn[j] = *(const float4*)(base + j * PLANE + p2);
        }
        unsigned long long vlo[CT], vhi[CT];
#pragma unroll
        for (int j = 0; j < CT; j++) {
            vlo[j] = pack2(v[j].x, v[j].y);
            vhi[j] = pack2(v[j].z, v[j].w);
        }
        int l0 = u & 0xff, l1 = (u >> 8) & 0xff;
        int l2 = (u >> 16) & 0xff, l3 = (u >> 24) & 0xff;
#pragma unroll
        for (int k = 0; k < NCLS; k++) {
            unsigned long long m01 = pack2((l0 == k) ? 1.0f : 0.0f,
                                           (l1 == k) ? 1.0f : 0.0f);
            unsigned long long m23 = pack2((l2 == k) ? 1.0f : 0.0f,
                                           (l3 == k) ? 1.0f : 0.0f);
#pragma unroll
            for (int j = 0; j < CT; j++) {
                acc[k][j] = ffma2(m01, vlo[j], acc[k][j]);
                acc[k][j] = ffma2(m23, vhi[j], acc[k][j]);
            }
        }
    }

    __shared__ float sred[8][NCLS * CT];
#pragma unroll
    for (int k = 0; k < NCLS; k++)
#pragma unroll
        for (int j = 0; j < CT; j++) {
            float lo, hi;
            unpack2(acc[k][j], lo, hi);
            float s = lo + hi;
#pragma unroll
            for (int off = 16; off; off >>= 1) s += __shfl_xor_sync(0xffffffffu, s, off);
            if (lane == 0) sred[w][k * CT + j] = s;
        }
    __syncthreads();
    if (tid < NCLS * CT) {
        float t = 0.0f;
#pragma unroll
        for (int w2 = 0; w2 < 8; w2++) t += sred[w2][tid];
        int k = tid / CT, j = tid % CT;
        g_sums_part[b * NCLS * CCH + k * CCH + c0 + j] = t;
    }
}

// ---------------- K3: e[k,n] = U @ F + per-class sumsq partials -----------------
// KEY: prototype L2-norm cancels in the loss (e_k/||e_k|| == p_hat_k.F/||p_hat_k.F||),
// so we use the UN-normalized EMA prototypes u[k,c], built in a reduction-free
// pre-phase here (k_protos kernel eliminated; k_logits now at ncu slot 3).
// block = 256 threads (8 warps). Warp pair (wp, wp+4) shares 128 px; halves
// split the 768 channels (384 each). 512 px/block, grid = 256 blocks.
// Table transposed spt[c][12] (9 + 3 pad floats, 48B rows): 3 broadcast
// LDS.128 per channel. spt region reused for cross-half accumulators.
__global__ void __launch_bounds__(256) k_logits(const float* __restrict__ feat,
                                                const float* __restrict__ proto0) {
    __shared__ float smemf[CCH * 12];           // 36864 B, dual-purpose
    float*  spt  = smemf;                       // [768][12] during channel loop
    float4* sacc = (float4*)smemf;              // [4][9][32] float4 afterwards
    float*  swq  = smemf + 4 * NCLS * 32 * 4;   // [4][9] (offset 4608 floats)

    int tid = threadIdx.x;
    // pre-phase: u[k,c] = cnt>0 ? 0.99*sum/max(cnt,1) + 0.01*p0 : p0
    for (int i = tid; i < NCLS * CCH; i += 256) {
        int c = i / NCLS, k = i - (i / NCLS) * NCLS;
        int cnt = g_counts[k];
        float inv = 0.99f / fmaxf((float)cnt, 1.0f);
        float s = 0.0f;
#pragma unroll
        for (int b = 0; b < 8; b++) s += g_sums_part[b * NCLS * CCH + k * CCH + c];
        float p0 = proto0[k * CCH + c];
        spt[c * 12 + k] = (cnt > 0) ? (inv * s + 0.01f * p0) : p0;
    }
    __syncthreads();

    int w = tid >> 5, lane = tid & 31;
    int wpair = w & 3, half = w >> 2;
    int px0 = blockIdx.x * 512 + wpair * 128;
    int b = px0 >> 14;
    int spx = (px0 & (PLANE - 1)) + lane * 4;
    const float* fb = feat + (size_t)b * CCH * PLANE + spx;
    int c0 = half * 384;

    unsigned long long alo[NCLS], ahi[NCLS];
#pragma unroll
    for (int k = 0; k < NCLS; k++) { alo[k] = 0ULL; ahi[k] = 0ULL; }

    // prefetch first 4 channels
    float4 vnext[4];
#pragma unroll
    for (int u = 0; u < 4; u++)
        vnext[u] = *(const float4*)(fb + (size_t)(c0 + u) * PLANE);

#pragma unroll 1
    for (int cc = 0; cc < 384; cc += 4) {
        float4 v[4];
#pragma unroll
        for (int u = 0; u < 4; u++) v[u] = vnext[u];
        if (cc < 380) {
#pragma unroll
            for (int u = 0; u < 4; u++)
                vnext[u] = *(const float4*)(fb + (size_t)(c0 + cc + 4 + u) * PLANE);
        }
#pragma unroll
        for (int u = 0; u < 4; u++) {
            unsigned long long vlo = pack2(v[u].x, v[u].y);
            unsigned long long vhi = pack2(v[u].z, v[u].w);
            const float4* pr = (const float4*)(spt + (c0 + cc + u) * 12);
            float4 p03 = pr[0], p47 = pr[1], p8x = pr[2];
            unsigned long long q;
            q = pack2(p03.x, p03.x); alo[0] = ffma2(q, vlo, alo[0]); ahi[0] = ffma2(q, vhi, ahi[0]);
            q = pack2(p03.y, p03.y); alo[1] = ffma2(q, vlo, alo[1]); ahi[1] = ffma2(q, vhi, ahi[1]);
            q = pack2(p03.z, p03.z); alo[2] = ffma2(q, vlo, alo[2]); ahi[2] = ffma2(q, vhi, ahi[2]);
            q = pack2(p03.w, p03.w); alo[3] = ffma2(q, vlo, alo[3]); ahi[3] = ffma2(q, vhi, ahi[3]);
            q = pack2(p47.x, p47.x); alo[4] = ffma2(q, vlo, alo[4]); ahi[4] = ffma2(q, vhi, ahi[4]);
            q = pack2(p47.y, p47.y); alo[5] = ffma2(q, vlo, alo[5]); ahi[5] = ffma2(q, vhi, ahi[5]);
            q = pack2(p47.z, p47.z); alo[6] = ffma2(q, vlo, alo[6]); ahi[6] = ffma2(q, vhi, ahi[6]);
            q = pack2(p47.w, p47.w); alo[7] = ffma2(q, vlo, alo[7]); ahi[7] = ffma2(q, vhi, ahi[7]);
            q = pack2(p8x.x, p8x.x); alo[8] = ffma2(q, vlo, alo[8]); ahi[8] = ffma2(q, vhi, ahi[8]);
        }
    }

    __syncthreads();   // all warps done reading spt; region becomes sacc/swq
    if (half == 1) {
#pragma unroll
        for (int k = 0; k < NCLS; k++) {
            float x0, x1, x2, x3;
            unpack2(alo[k], x0, x1);
            unpack2(ahi[k], x2, x3);
            sacc[(wpair * NCLS + k) * 32 + lane] = make_float4(x0, x1, x2, x3);
        }
    }
    __syncthreads();
    if (half == 0) {
#pragma unroll
        for (int k = 0; k < NCLS; k++) {
            float x0, x1, x2, x3;
            unpack2(alo[k], x0, x1);
            unpack2(ahi[k], x2, x3);
            float4 o2 = sacc[(wpair * NCLS + k) * 32 + lane];
            x0 += o2.x; x1 += o2.y; x2 += o2.z; x3 += o2.w;
            *(float4*)(g_d + (size_t)k * PIX + px0 + lane * 4) =
                make_float4(x0, x1, x2, x3);
            float q = x0 * x0 + x1 * x1 + x2 * x2 + x3 * x3;
#pragma unroll
            for (int off = 16; off; off >>= 1) q += __shfl_xor_sync(0xffffffffu, q, off);
            if (lane == 0) swq[wpair * NCLS + k] = q;
        }
    }
    __syncthreads();
    if (tid < NCLS) {
        float q = swq[0 * NCLS + tid] + swq[1 * NCLS + tid] +
                  swq[2 * NCLS + tid] + swq[3 * NCLS + tid];
        g_rssq_part[tid * 256 + blockIdx.x] = q;
    }
}

// ---------------- K3b: per-class scale = 1/(max(||row||,eps)*T) -----------------
__global__ void k_scale() {
    int tid = threadIdx.x;
    int k = tid >> 5, lane = tid & 31;
    if (k >= NCLS) return;
    float s = 0.0f;
#pragma unroll
    for (int j = 0; j < 8; j++) s += g_rssq_part[k * 256 + lane + 32 * j];
#pragma unroll
    for (int off = 16; off; off >>= 1) s += __shfl_xor_sync(0xffffffffu, s, off);
    if (lane == 0) g_scale[k] = 1.0f / (fmaxf(sqrtf(s), 1e-12f) * 0.1f);
}

// ---------------- K4: log-softmax, pick label, block partial (4 px/thread) ------
__global__ void __launch_bounds__(256) k_loss() {
    __shared__ float ssc[NCLS];
    __shared__ float sred[256];
    int tid = threadIdx.x;
    if (tid < NCLS) ssc[tid] = g_scale[tid];
    __syncthreads();
    int n = (blockIdx.x * 256 + tid) * 4;          // grid = 128 blocks
    float4 x[NCLS];
#pragma unroll
    for (int k = 0; k < NCLS; k++) {
        float4 t = *(const float4*)(g_d + (size_t)k * PIX + n);
        float sc = ssc[k];
        x[k] = make_float4(t.x * sc, t.y * sc, t.z * sc, t.w * sc);
    }
    uchar4 lb = *(const uchar4*)(g_labels + n);
    int labs[4] = {lb.x, lb.y, lb.z, lb.w};
    float acc = 0.0f;
#pragma unroll
    for (int e = 0; e < 4; e++) {
        float xe[NCLS];
#pragma unroll
        for (int k = 0; k < NCLS; k++)
            xe[k] = (e == 0) ? x[k].x : (e == 1) ? x[k].y : (e == 2) ? x[k].z : x[k].w;
        float m = -1e30f;
#pragma unroll
        for (int k = 0; k < NCLS; k++) m = fmaxf(m, xe[k]);
        float se = 0.0f;
#pragma unroll
        for (int k = 0; k < NCLS; k++) se += __expf(xe[k] - m);
        acc += xe[labs[e]] - (m + __logf(se));
    }
    sred[tid] = acc;
    __syncthreads();
#pragma unroll
    for (int s = 128; s; s >>= 1) {
        if (tid < s) sred[tid] += sred[tid + s];
        __syncthreads();
    }
    if (tid == 0) g_partials[blockIdx.x] = sred[0];
}

// ---------------- K5: final deterministic reduction -----------------------------
__global__ void k_final(float* __restrict__ out) {
    __shared__ float sred[128];
    int tid = threadIdx.x;
    sred[tid] = g_partials[tid];
    __syncthreads();
#pragma unroll
    for (int s = 64; s; s >>= 1) {
        if (tid < s) sred[tid] += sred[tid + s];
        __syncthreads();
    }
    if (tid == 0) out[0] = -sred[0] * (1.0f / (float)PIX);
}

// ---------------- launch --------------------------------------------------------
extern "C" void kernel_launch(void* const* d_in, const int* in_sizes, int n_in,
                              void* d_out, int out_size) {
    const float* feat   = (const float*)d_in[0];
    const int*   gt32   = (const int*)d_in[1];   // int32 or int64, probed
    const float* proto0 = (const float*)d_in[2];
    float* out = (float*)d_out;

    k_init  <<<1,    256>>>(gt32);
    k_labels<<<512,  256>>>(gt32);
    k_sums  <<<2048, 256>>>(feat);
    k_logits<<<256,  256>>>(feat, proto0);       // ncu slot (launch idx 3)
    k_scale <<<1,    288>>>();
    k_loss  <<<128,  256>>>();
    k_final <<<1,    128>>>(out);
}

// round 16
// speedup vs baseline: 1.0780x; 1.0780x over previous
#include <cuda_runtime.h>
#include <cuda_bf16.h>
#include <math.h>

#define NCLS 9
#define CCH  768
#define PIX  131072     // 8 * 128 * 128 downsampled pixels
#define PLANE 16384     // 128*128
#define CT   3          // channels per k_sums tile (768 = 256 * 3)

// ---------------- scratch (device globals; no allocation allowed) -------------
// layout: g_sums_part[(k*CCH + c)*8 + b]  (b innermost -> float4-pair loads)
__device__ float         g_sums_part[NCLS * CCH * 8];
__device__ int           g_counts[NCLS];
__device__ unsigned char g_labels[PIX];
__device__ float         g_d[NCLS * PIX];               // 4.7 MB e-matrix (pre-norm)
__device__ float         g_rssq_part[NCLS * 256];
__device__ float         g_scale[NCLS];
__device__ float         g_partials[128];
__device__ int           g_is_i32;

// ---------------- f32x2 packed helpers ----------------------------------------
__device__ __forceinline__ unsigned long long pack2(float x, float y) {
    unsigned long long d;
    asm("mov.b64 %0, {%1, %2};" : "=l"(d) : "f"(x), "f"(y));
    return d;
}
__device__ __forceinline__ void unpack2(unsigned long long v, float& x, float& y) {
    asm("mov.b64 {%0, %1}, %2;" : "=f"(x), "=f"(y) : "l"(v));
}
__device__ __forceinline__ unsigned long long ffma2(unsigned long long a,
                                                    unsigned long long b,
                                                    unsigned long long c) {
    unsigned long long d;
    asm("fma.rn.f32x2 %0, %1, %2, %3;" : "=l"(d) : "l"(a), "l"(b), "l"(c));
    return d;
}

// ---------------- K_init: zero counters + gt dtype probe ----------------------
__global__ void k_init(const int* __restrict__ gt32) {
    int tid = threadIdx.x;
    if (tid < NCLS) g_counts[tid] = 0;
    // int64 gt (little-endian): odd 32-bit words are all 0.
    // int32 gt: odd words are labels in [0,9): P(all 2048 zero) ~ (1/9)^2048.
    int f = 0;
    for (int i = tid; i < 2048; i += 256) f |= gt32[2 * i + 1];
    __shared__ int sf;
    if (tid == 0) sf = 0;
    __syncthreads();
    if (f) atomicOr(&sf, 1);
    __syncthreads();
    if (tid == 0) g_is_i32 = (sf != 0);
}

// ---------------- K0: downsampled labels + histogram ---------------------------
__global__ void k_labels(const int* __restrict__ gt32) {
    __shared__ int sh[NCLS];
    int tid = threadIdx.x;
    if (tid < NCLS) sh[tid] = 0;
    __syncthreads();
    int n = blockIdx.x * 256 + tid;                 // grid = 512 blocks
    int b = n >> 14, r = n & (PLANE - 1);
    int h = r >> 7, w = r & 127;
    int idx = b * 262144 + h * 2048 + w * 4;        // gt[b, 4h, 4w] element index
    int lab = g_is_i32 ? gt32[idx] : gt32[2 * idx]; // int64: low word
    g_labels[n] = (unsigned char)lab;
    atomicAdd(&sh[lab], 1);
    __syncthreads();
    if (tid < NCLS) atomicAdd(&g_counts[tid], sh[tid]);
}

// ---------------- K1: per-class channel sums (register one-hot accumulate) -----
// grid = 2048: bid = b + 8*ctile (ctile in [0,256), CT=3 channels each).
// Each block owns its (b, k, c0..c0+2) slots exclusively: no atomics.
// float4-widened single-prefetch structure (validated 79.6us, DRAM 64.6%).
__global__ void __launch_bounds__(256, 2) k_sums(const float* __restrict__ feat) {
    int bid = blockIdx.x;
    int b = bid & 7;
    int c0 = (bid >> 3) * CT;
    int tid = threadIdx.x, w = tid >> 5, lane = tid & 31;
    const float* base = feat + (size_t)(b * CCH + c0) * PLANE;
    const unsigned int* lab32 = (const unsigned int*)(g_labels + b * PLANE);

    unsigned long long acc[NCLS][CT];
#pragma unroll
    for (int k = 0; k < NCLS; k++)
#pragma unroll
        for (int j = 0; j < CT; j++) acc[k][j] = 0ULL;

    int pix0 = w * 2048 + lane * 4;

    // prefetch group 0 (128 px per warp per group)
    unsigned int un = lab32[pix0 >> 2];
    float4 vn[CT];
#pragma unroll
    for (int j = 0; j < CT; j++) vn[j] = *(const float4*)(base + j * PLANE + pix0);

#pragma unroll 2
    for (int g = 0; g < 16; ++g) {
        unsigned int u = un;
        float4 v[CT];
#pragma unroll
        for (int j = 0; j < CT; j++) v[j] = vn[j];
        if (g < 15) {
            int p2 = pix0 + (g + 1) * 128;
            un = lab32[p2 >> 2];
#pragma unroll
            for (int j = 0; j < CT; j++) vn[j] = *(const float4*)(base + j * PLANE + p2);
        }
        unsigned long long vlo[CT], vhi[CT];
#pragma unroll
        for (int j = 0; j < CT; j++) {
            vlo[j] = pack2(v[j].x, v[j].y);
            vhi[j] = pack2(v[j].z, v[j].w);
        }
        int l0 = u & 0xff, l1 = (u >> 8) & 0xff;
        int l2 = (u >> 16) & 0xff, l3 = (u >> 24) & 0xff;
#pragma unroll
        for (int k = 0; k < NCLS; k++) {
            unsigned long long m01 = pack2((l0 == k) ? 1.0f : 0.0f,
                                           (l1 == k) ? 1.0f : 0.0f);
            unsigned long long m23 = pack2((l2 == k) ? 1.0f : 0.0f,
                                           (l3 == k) ? 1.0f : 0.0f);
#pragma unroll
            for (int j = 0; j < CT; j++) {
                acc[k][j] = ffma2(m01, vlo[j], acc[k][j]);
                acc[k][j] = ffma2(m23, vhi[j], acc[k][j]);
            }
        }
    }

    __shared__ float sred[8][NCLS * CT];
#pragma unroll
    for (int k = 0; k < NCLS; k++)
#pragma unroll
        for (int j = 0; j < CT; j++) {
            float lo, hi;
            unpack2(acc[k][j], lo, hi);
            float s = lo + hi;
#pragma unroll
            for (int off = 16; off; off >>= 1) s += __shfl_xor_sync(0xffffffffu, s, off);
            if (lane == 0) sred[w][k * CT + j] = s;
        }
    __syncthreads();
    if (tid < NCLS * CT) {
        float t = 0.0f;
#pragma unroll
        for (int w2 = 0; w2 < 8; w2++) t += sred[w2][tid];
        int k = tid / CT, j = tid % CT;
        g_sums_part[(k * CCH + c0 + j) * 8 + b] = t;   // b innermost
    }
}

// ---------------- K3: e[k,n] = U @ F + per-class sumsq partials -----------------
// Prototype L2-norm cancels in the loss (e_k/||e_k|| invariant), so use the
// UN-normalized EMA prototypes u[k,c], built in a cheap pre-phase: the 8
// batch-partials per (k,c) are contiguous -> 2x LDG.128 per entry.
// block = 256 threads (8 warps). Warp pair (wp, wp+4) shares 128 px; halves
// split the 768 channels (384 each). 512 px/block, grid = 256 blocks.
// DEPTH-8 channel prefetch (~4 KB in flight per warp).
__global__ void __launch_bounds__(256) k_logits(const float* __restrict__ feat,
                                                const float* __restrict__ proto0) {
    __shared__ float smemf[CCH * 12];           // 36864 B, dual-purpose
    float*  spt  = smemf;                       // [768][12] during channel loop
    float4* sacc = (float4*)smemf;              // [4][9][32] float4 afterwards
    float*  swq  = smemf + 4 * NCLS * 32 * 4;   // [4][9] (offset 4608 floats)

    int tid = threadIdx.x;
    // pre-phase: u[k,c] = cnt>0 ? 0.99*sum/max(cnt,1) + 0.01*p0 : p0
    for (int i = tid; i < NCLS * CCH; i += 256) {
        int c = i / NCLS, k = i - (i / NCLS) * NCLS;
        int cnt = g_counts[k];
        float inv = 0.99f / fmaxf((float)cnt, 1.0f);
        const float4* sp = (const float4*)(g_sums_part + (k * CCH + c) * 8);
        float4 a = sp[0], d = sp[1];
        float s = ((a.x + a.y) + (a.z + a.w)) + ((d.x + d.y) + (d.z + d.w));
        float p0 = proto0[k * CCH + c];
        spt[c * 12 + k] = (cnt > 0) ? (inv * s + 0.01f * p0) : p0;
    }
    __syncthreads();

    int w = tid >> 5, lane = tid & 31;
    int wpair = w & 3, half = w >> 2;
    int px0 = blockIdx.x * 512 + wpair * 128;
    int b = px0 >> 14;
    int spx = (px0 & (PLANE - 1)) + lane * 4;
    const float* fb = feat + (size_t)b * CCH * PLANE + spx;
    int c0 = half * 384;

    unsigned long long alo[NCLS], ahi[NCLS];
#pragma unroll
    for (int k = 0; k < NCLS; k++) { alo[k] = 0ULL; ahi[k] = 0ULL; }

    // prefetch first 8 channels
    float4 vnext[8];
#pragma unroll
    for (int u = 0; u < 8; u++)
        vnext[u] = *(const float4*)(fb + (size_t)(c0 + u) * PLANE);

#pragma unroll 1
    for (int cc = 0; cc < 384; cc += 8) {
        float4 v[8];
#pragma unroll
        for (int u = 0; u < 8; u++) v[u] = vnext[u];
        if (cc < 376) {
#pragma unroll
            for (int u = 0; u < 8; u++)
                vnext[u] = *(const float4*)(fb + (size_t)(c0 + cc + 8 + u) * PLANE);
        }
#pragma unroll
        for (int u = 0; u < 8; u++) {
            unsigned long long vlo = pack2(v[u].x, v[u].y);
            unsigned long long vhi = pack2(v[u].z, v[u].w);
            const float4* pr = (const float4*)(spt + (c0 + cc + u) * 12);
            float4 p03 = pr[0], p47 = pr[1], p8x = pr[2];
            unsigned long long q;
            q = pack2(p03.x, p03.x); alo[0] = ffma2(q, vlo, alo[0]); ahi[0] = ffma2(q, vhi, ahi[0]);
            q = pack2(p03.y, p03.y); alo[1] = ffma2(q, vlo, alo[1]); ahi[1] = ffma2(q, vhi, ahi[1]);
            q = pack2(p03.z, p03.z); alo[2] = ffma2(q, vlo, alo[2]); ahi[2] = ffma2(q, vhi, ahi[2]);
            q = pack2(p03.w, p03.w); alo[3] = ffma2(q, vlo, alo[3]); ahi[3] = ffma2(q, vhi, ahi[3]);
            q = pack2(p47.x, p47.x); alo[4] = ffma2(q, vlo, alo[4]); ahi[4] = ffma2(q, vhi, ahi[4]);
            q = pack2(p47.y, p47.y); alo[5] = ffma2(q, vlo, alo[5]); ahi[5] = ffma2(q, vhi, ahi[5]);
            q = pack2(p47.z, p47.z); alo[6] = ffma2(q, vlo, alo[6]); ahi[6] = ffma2(q, vhi, ahi[6]);
            q = pack2(p47.w, p47.w); alo[7] = ffma2(q, vlo, alo[7]); ahi[7] = ffma2(q, vhi, ahi[7]);
            q = pack2(p8x.x, p8x.x); alo[8] = ffma2(q, vlo, alo[8]); ahi[8] = ffma2(q, vhi, ahi[8]);
        }
    }

    __syncthreads();   // all warps done reading spt; region becomes sacc/swq
    if (half == 1) {
#pragma unroll
        for (int k = 0; k < NCLS; k++) {
            float x0, x1, x2, x3;
            unpack2(alo[k], x0, x1);
            unpack2(ahi[k], x2, x3);
            sacc[(wpair * NCLS + k) * 32 + lane] = make_float4(x0, x1, x2, x3);
        }
    }
    __syncthreads();
    if (half == 0) {
#pragma unroll
        for (int k = 0; k < NCLS; k++) {
            float x0, x1, x2, x3;
            unpack2(alo[k], x0, x1);
            unpack2(ahi[k], x2, x3);
            float4 o2 = sacc[(wpair * NCLS + k) * 32 + lane];
            x0 += o2.x; x1 += o2.y; x2 += o2.z; x3 += o2.w;
            *(float4*)(g_d + (size_t)k * PIX + px0 + lane * 4) =
                make_float4(x0, x1, x2, x3);
            float q = x0 * x0 + x1 * x1 + x2 * x2 + x3 * x3;
#pragma unroll
            for (int off = 16; off; off >>= 1) q += __shfl_xor_sync(0xffffffffu, q, off);
            if (lane == 0) swq[wpair * NCLS + k] = q;
        }
    }
    __syncthreads();
    if (tid < NCLS) {
        float q = swq[0 * NCLS + tid] + swq[1 * NCLS + tid] +
                  swq[2 * NCLS + tid] + swq[3 * NCLS + tid];
        g_rssq_part[tid * 256 + blockIdx.x] = q;
    }
}

// ---------------- K3b: per-class scale = 1/(max(||row||,eps)*T) -----------------
__global__ void k_scale() {
    int tid = threadIdx.x;
    int k = tid >> 5, lane = tid & 31;
    if (k >= NCLS) return;
    float s = 0.0f;
#pragma unroll
    for (int j = 0; j < 8; j++) s += g_rssq_part[k * 256 + lane + 32 * j];
#pragma unroll
    for (int off = 16; off; off >>= 1) s += __shfl_xor_sync(0xffffffffu, s, off);
    if (lane == 0) g_scale[k] = 1.0f / (fmaxf(sqrtf(s), 1e-12f) * 0.1f);
}

// ---------------- K4: log-softmax, pick label, block partial (4 px/thread) ------
__global__ void __launch_bounds__(256) k_loss() {
    __shared__ float ssc[NCLS];
    __shared__ float sred[256];
    int tid = threadIdx.x;
    if (tid < NCLS) ssc[tid] = g_scale[tid];
    __syncthreads();
    int n = (blockIdx.x * 256 + tid) * 4;          // grid = 128 blocks
    float4 x[NCLS];
#pragma unroll
    for (int k = 0; k < NCLS; k++) {
        float4 t = *(const float4*)(g_d + (size_t)k * PIX + n);
        float sc = ssc[k];
        x[k] = make_float4(t.x * sc, t.y * sc, t.z * sc, t.w * sc);
    }
    uchar4 lb = *(const uchar4*)(g_labels + n);
    int labs[4] = {lb.x, lb.y, lb.z, lb.w};
    float acc = 0.0f;
#pragma unroll
    for (int e = 0; e < 4; e++) {
        float xe[NCLS];
#pragma unroll
        for (int k = 0; k < NCLS; k++)
            xe[k] = (e == 0) ? x[k].x : (e == 1) ? x[k].y : (e == 2) ? x[k].z : x[k].w;
        float m = -1e30f;
#pragma unroll
        for (int k = 0; k < NCLS; k++) m = fmaxf(m, xe[k]);
        float se = 0.0f;
#pragma unroll
        for (int k = 0; k < NCLS; k++) se += __expf(xe[k] - m);
        acc += xe[labs[e]] - (m + __logf(se));
    }
    sred[tid] = acc;
    __syncthreads();
#pragma unroll
    for (int s = 128; s; s >>= 1) {
        if (tid < s) sred[tid] += sred[tid + s];
        __syncthreads();
    }
    if (tid == 0) g_partials[blockIdx.x] = sred[0];
}

// ---------------- K5: final deterministic reduction -----------------------------
__global__ void k_final(float* __restrict__ out) {
    __shared__ float sred[128];
    int tid = threadIdx.x;
    sred[tid] = g_partials[tid];
    __syncthreads();
#pragma unroll
    for (int s = 64; s; s >>= 1) {
        if (tid < s) sred[tid] += sred[tid + s];
        __syncthreads();
    }
    if (tid == 0) out[0] = -sred[0] * (1.0f / (float)PIX);
}

// ---------------- launch --------------------------------------------------------
extern "C" void kernel_launch(void* const* d_in, const int* in_sizes, int n_in,
                              void* d_out, int out_size) {
    const float* feat   = (const float*)d_in[0];
    const int*   gt32   = (const int*)d_in[1];   // int32 or int64, probed
    const float* proto0 = (const float*)d_in[2];
    float* out = (float*)d_out;

    k_init  <<<1,    256>>>(gt32);
    k_labels<<<512,  256>>>(gt32);
    k_sums  <<<2048, 256>>>(feat);
    k_logits<<<256,  256>>>(feat, proto0);       // ncu slot (launch idx 3)
    k_scale <<<1,    288>>>();
    k_loss  <<<128,  256>>>();
    k_final <<<1,    128>>>(out);
}